// round 7
// baseline (speedup 1.0000x reference)
#include <cuda_runtime.h>
#include <cstdint>

#define BB 16
#define TT 512
#define DD 384
#define OUT_LEN 3584            // T * (MAX_DUR - 1)
#define ROW_BYTES (DD * 4)      // 1536
#define ROWS 8                  // output rows per gather block
#define BLOCKS_PER_B (OUT_LEN / ROWS)   // 448
#define NT 128
#define V4 (DD / 4)             // 96 float4 per row

// Inverse map: source row per output row, -1 = pad. 229 KB, L2-resident.
__device__ int g_row_src[BB * OUT_LEN];

// ---------------------------------------------------------------------------
// Kernel A: per-batch masked cumsum (shfl scan, 128 threads) + inverse-map
// scatter. One block per batch.
// ---------------------------------------------------------------------------
__global__ void __launch_bounds__(NT)
lr_scan(const int* __restrict__ ds, const int* __restrict__ ilens) {
    __shared__ int wtot[4];
    const int b = blockIdx.x;
    const int tid = threadIdx.x;
    const int lane = tid & 31;
    const int w = tid >> 5;

    const int ilen = ilens[b];
    int4 dv = ((const int4*)(ds + b * TT))[tid];
    const int g0 = tid * 4;
    int d0 = (g0 + 0 < ilen) ? dv.x : 0;
    int d1 = (g0 + 1 < ilen) ? dv.y : 0;
    int d2 = (g0 + 2 < ilen) ? dv.z : 0;
    int d3 = (g0 + 3 < ilen) ? dv.w : 0;
    int p1 = d0 + d1, p2 = p1 + d2, p3 = p2 + d3;

    // Init this batch's row_src to -1 (896 int4 over 128 threads).
    int4* row4 = (int4*)(g_row_src + b * OUT_LEN);
    const int4 neg1 = make_int4(-1, -1, -1, -1);
    #pragma unroll
    for (int i = tid; i < OUT_LEN / 4; i += NT) row4[i] = neg1;

    // Block scan of per-thread sums.
    int x = p3;
    #pragma unroll
    for (int off = 1; off < 32; off <<= 1) {
        int y = __shfl_up_sync(0xFFFFFFFFu, x, off);
        if (lane >= off) x += y;
    }
    if (lane == 31) wtot[w] = x;
    __syncthreads();                       // also orders init before scatter
    int woff = 0;
    #pragma unroll
    for (int i = 0; i < 4; ++i) woff += (i < w) ? wtot[i] : 0;
    const int excl = woff + x - p3;
    __syncthreads();                       // all inits done before any scatter

    // Scatter: position t occupies output rows [start, end).
    int* row = g_row_src + b * OUT_LEN;
    int s = excl;
    int e0 = excl + d0, e1 = excl + p1, e2 = excl + p2, e3 = excl + p3;
    for (int j = s;  j < e0; ++j) row[j] = g0 + 0;
    for (int j = e0; j < e1; ++j) row[j] = g0 + 1;
    for (int j = e1; j < e2; ++j) row[j] = g0 + 2;
    for (int j = e2; j < e3; ++j) row[j] = g0 + 3;
}

// ---------------------------------------------------------------------------
// Kernel B: gather. Tiny smem (12.3 KB) -> 16 CTAs/SM. Each thread:
// 6x (row_src LDG.32 -> xs LDG.128 -> STS.128), then one 12 KB TMA store.
// ---------------------------------------------------------------------------
__global__ void __launch_bounds__(NT)
lr_gather(const float* __restrict__ xs, float* __restrict__ out) {
    __shared__ alignas(128) float4 buf[ROWS * V4];   // 12288 B

    const int tid = threadIdx.x;
    const int b = blockIdx.y;
    const int r0 = blockIdx.x * ROWS;

    const int* __restrict__ rs = g_row_src + b * OUT_LEN + r0;
    const float4* __restrict__ xb = (const float4*)xs + (size_t)b * TT * V4;

    #pragma unroll
    for (int i = 0; i < (ROWS * V4) / NT; ++i) {     // 6 iters
        const int f = tid + i * NT;
        const int rl = f / V4;
        const int c = f - rl * V4;
        const int s = rs[rl];                        // L2-hit LDG.32
        float4 v = make_float4(0.f, 0.f, 0.f, 0.f);
        if (s >= 0) v = xb[s * V4 + c];              // coalesced LDG.128
        buf[f] = v;
    }
    __syncthreads();

    if (tid == 0) {
        uint32_t buf_s = (uint32_t)__cvta_generic_to_shared(buf);
        asm volatile("fence.proxy.async.shared::cta;" ::: "memory");
        char* dst = (char*)(out + ((size_t)b * OUT_LEN + r0) * DD);
        asm volatile(
            "cp.async.bulk.global.shared::cta.bulk_group [%0], [%1], %2;"
            :: "l"(dst), "r"(buf_s), "r"((uint32_t)(ROWS * ROW_BYTES)) : "memory");
        asm volatile("cp.async.bulk.commit_group;" ::: "memory");
        asm volatile("cp.async.bulk.wait_group.read 0;" ::: "memory");
    }
}

extern "C" void kernel_launch(void* const* d_in, const int* in_sizes, int n_in,
                              void* d_out, int out_size) {
    const float* xs = (const float*)d_in[0];
    const int* ds = (const int*)d_in[1];
    const int* ilens = (const int*)d_in[2];
    float* out = (float*)d_out;

    lr_scan<<<BB, NT>>>(ds, ilens);
    dim3 grid(BLOCKS_PER_B, BB);    // (448, 16)
    lr_gather<<<grid, NT>>>(xs, out);
}

// round 8
// speedup vs baseline: 1.1235x; 1.1235x over previous
#include <cuda_runtime.h>
#include <cstdint>

#define BB 16
#define TT 512
#define DD 384
#define OUT_LEN 3584            // T * (MAX_DUR - 1)
#define ROWS 8                  // output rows per block
#define BLOCKS_PER_B (OUT_LEN / ROWS)   // 448
#define NT 128
#define V4 (DD / 4)             // 96 float4 per row

// Fully fused: block scan of ds (L2-resident) + searchsorted + direct
// LDG.128->STG.128 gather. No TMA, no smem data buffer, 2.1 KB smem.
__global__ void __launch_bounds__(NT, 12)
lr_fused(const float* __restrict__ xs, const int* __restrict__ ds,
         const int* __restrict__ ilens, float* __restrict__ out) {
    __shared__ int csum[TT];
    __shared__ int wtot[4];
    __shared__ int srcs[ROWS];

    const int tid = threadIdx.x;
    const int lane = tid & 31;
    const int w = tid >> 5;
    const int b = blockIdx.y;
    const int r0 = blockIdx.x * ROWS;

    // ---- masked duration load: 4 consecutive per thread ----
    const int ilen = __ldg(ilens + b);
    int4 dv = ((const int4*)(ds + b * TT))[tid];
    const int g0 = tid * 4;
    int d0 = (g0 + 0 < ilen) ? dv.x : 0;
    int d1 = (g0 + 1 < ilen) ? dv.y : 0;
    int d2 = (g0 + 2 < ilen) ? dv.z : 0;
    int d3 = (g0 + 3 < ilen) ? dv.w : 0;
    int p1 = d0 + d1, p2 = p1 + d2, p3 = p2 + d3;

    // ---- block inclusive scan -> csum ----
    int x = p3;
    #pragma unroll
    for (int off = 1; off < 32; off <<= 1) {
        int y = __shfl_up_sync(0xFFFFFFFFu, x, off);
        if (lane >= off) x += y;
    }
    if (lane == 31) wtot[w] = x;
    __syncthreads();
    int woff = 0;
    #pragma unroll
    for (int i = 0; i < 4; ++i) woff += (i < w) ? wtot[i] : 0;
    const int excl = woff + x - p3;
    csum[g0 + 0] = excl + d0;
    csum[g0 + 1] = excl + p1;
    csum[g0 + 2] = excl + p2;
    csum[g0 + 3] = excl + p3;
    __syncthreads();

    const int total = csum[TT - 1];
    const int p = min(max(total - r0, 0), ROWS);   // valid rows are a prefix

    // ---- searchsorted(csum, t, 'right'): 10 halvings for [0,512] ----
    if (tid < ROWS) {
        int s = -1;
        if (tid < p) {
            const int t = r0 + tid;
            int lo = 0, hi = TT;
            #pragma unroll
            for (int it = 0; it < 10; ++it) {
                int mid = (lo + hi) >> 1;
                if (csum[mid] <= t) lo = mid + 1; else hi = mid;
            }
            s = lo;
        }
        srcs[tid] = s;
    }
    __syncthreads();

    // ---- gather: 768 float4 over 128 threads, direct LDG->STG ----
    // Output rows are contiguous: flat index f maps straight to ob[f].
    const float4* __restrict__ xb = (const float4*)xs + (size_t)b * TT * V4;
    float4* __restrict__ ob = (float4*)out + ((size_t)b * OUT_LEN + r0) * V4;

    #pragma unroll
    for (int i = 0; i < (ROWS * V4) / NT; ++i) {     // 6 iters
        const int f = tid + i * NT;
        const int rl = f / V4;                        // mul-shift (const div)
        const int c = f - rl * V4;
        const int s = srcs[rl];
        float4 v = make_float4(0.f, 0.f, 0.f, 0.f);
        if (s >= 0) v = xb[s * V4 + c];               // coalesced, dups hit L1
        ob[f] = v;                                    // fully coalesced STG.128
    }
}

extern "C" void kernel_launch(void* const* d_in, const int* in_sizes, int n_in,
                              void* d_out, int out_size) {
    const float* xs = (const float*)d_in[0];
    const int* ds = (const int*)d_in[1];
    const int* ilens = (const int*)d_in[2];
    float* out = (float*)d_out;

    dim3 grid(BLOCKS_PER_B, BB);    // (448, 16)
    lr_fused<<<grid, NT>>>(xs, ds, ilens, out);
}